// round 14
// baseline (speedup 1.0000x reference)
#include <cuda_runtime.h>
#include <math.h>

// Problem constants
#define Bv   16
#define Cv   64
#define Hv   256
#define Wv   256
#define Kv   7
#define HIDv 16
#define NCH  (Bv * Cv)          // 1024 channels
#define HWv  (Hv * Wv)          // 65536
#define KK   (Kv * Kv)          // 49
#define COLS (Cv * KK)          // 3136

// Conv tiling: persistent block over 4 vertical tiles of 128x32.
#define TILE_W 128
#define TILE_H 32
#define NT 4
#define CPT 4
#define RPT 4
#define IN_ROWS (RPT + 6)        // 10
#define SROWS (TILE_H + 6)       // 38
#define SSTRIDE 136              // smem col c holds global col x0-4+c

// Scratch (no cudaMalloc allowed)
__device__ float g_pooled[NCH];
__device__ float g_wbuf[NCH * KK];

// ---------------------------------------------------------------------------
// Kernel 1: global average pool for a 512-channel group.
// ---------------------------------------------------------------------------
__global__ void gap_kernel(const float* __restrict__ x, int ch0) {
    const int ch = ch0 + blockIdx.x;
    const float4* p = reinterpret_cast<const float4*>(x + (size_t)ch * HWv);
    float s = 0.f;
    #pragma unroll 8
    for (int i = threadIdx.x; i < HWv / 4; i += 512) {
        float4 v = p[i];
        s += (v.x + v.y) + (v.z + v.w);
    }
    #pragma unroll
    for (int off = 16; off > 0; off >>= 1)
        s += __shfl_xor_sync(0xffffffffu, s, off);
    __shared__ float red[16];
    const int lane = threadIdx.x & 31, wid = threadIdx.x >> 5;
    if (lane == 0) red[wid] = s;
    __syncthreads();
    if (threadIdx.x == 0) {
        float t = 0.f;
        #pragma unroll
        for (int i = 0; i < 16; ++i) t += red[i];
        g_pooled[ch] = t * (1.0f / (float)HWv);
    }
}

// ---------------------------------------------------------------------------
// Kernel 2: MLP weight generator for an 8-batch group (batches b0..b0+7).
// ---------------------------------------------------------------------------
__global__ void mlp_kernel(const float* __restrict__ w1, const float* __restrict__ b1,
                           const float* __restrict__ w2, const float* __restrict__ b2,
                           int b0) {
    __shared__ float sp[8 * Cv];     // pooled for 8 batches
    __shared__ float sh[8 * HIDv];   // hdn for 8 batches
    const int tid = threadIdx.x;

    for (int i = tid; i < 8 * Cv; i += 256) sp[i] = g_pooled[b0 * Cv + i];
    __syncthreads();

    if (tid < 8 * HIDv) {            // one thread per hdn element
        const int b = tid >> 4, h = tid & 15;
        float s = b1[h];
        #pragma unroll
        for (int c = 0; c < Cv; ++c)
            s = fmaf(sp[b * Cv + c], w1[c * HIDv + h], s);
        sh[tid] = 0.5f * s * (1.0f + erff(s * 0.70710678118654752f));
    }
    __syncthreads();

    const int j0 = blockIdx.x * 49;  // 64 blocks * 49 = 3136
    for (int t = tid; t < 49 * 8; t += 256) {
        const int jl = t >> 3, b = t & 7;
        const int j = j0 + jl;
        float s = b2[j];
        #pragma unroll
        for (int h = 0; h < HIDv; ++h)
            s = fmaf(sh[b * HIDv + h], w2[h * COLS + j], s);
        g_wbuf[(b0 + b) * COLS + j] = 1.0f / (1.0f + __expf(-s));
    }
}

// ---------------------------------------------------------------------------
// cp.async helpers + vectorized tile loader (R11, proven)
// ---------------------------------------------------------------------------
__device__ __forceinline__ int reflect_idx(int i) {
    return i < 0 ? -i : (i > 255 ? 510 - i : i);
}
__device__ __forceinline__ void cpasync4(float* dst_smem, const float* src_gmem) {
    unsigned dst = (unsigned)__cvta_generic_to_shared(dst_smem);
    asm volatile("cp.async.ca.shared.global [%0], [%1], 4;" :: "r"(dst), "l"(src_gmem));
}
__device__ __forceinline__ void cpasync16(float* dst_smem, const float* src_gmem) {
    unsigned dst = (unsigned)__cvta_generic_to_shared(dst_smem);
    asm volatile("cp.async.cg.shared.global [%0], [%1], 16;" :: "r"(dst), "l"(src_gmem));
}
__device__ __forceinline__ void load_tile_async(float* __restrict__ buf,
                                                const float* __restrict__ xc,
                                                int x0, int y0, int tx, int ty) {
    for (int r = ty; r < SROWS; r += 8) {
        const int gr = reflect_idx(y0 - 3 + r);
        const float* __restrict__ rowp = xc + gr * Wv;
        float* __restrict__ srow = buf + r * SSTRIDE;
        cpasync16(srow + 4 + 4 * tx, rowp + x0 + 4 * tx);
        if (tx < 6) {
            const int c = (tx < 3) ? (tx + 1) : (129 + tx);
            cpasync4(srow + c, rowp + reflect_idx(x0 - 4 + c));
        }
    }
}

// ---------------------------------------------------------------------------
// Kernel 3: depthwise 7x7 conv, reflect padding (R11 structure, proven floor).
// ---------------------------------------------------------------------------
template<int R>
__device__ __forceinline__ void conv_row_step(const float* __restrict__ row,
                                              const float (&w)[KK],
                                              float4 (&acc)[RPT]) {
    float v[12];
    {
        float4 t0 = *reinterpret_cast<const float4*>(row);
        float4 t1 = *reinterpret_cast<const float4*>(row + 4);
        float4 t2 = *reinterpret_cast<const float4*>(row + 8);
        v[0] = t0.x; v[1] = t0.y; v[2]  = t0.z; v[3]  = t0.w;
        v[4] = t1.x; v[5] = t1.y; v[6]  = t1.z; v[7]  = t1.w;
        v[8] = t2.x; v[9] = t2.y; v[10] = t2.z; v[11] = t2.w;
    }
    constexpr int OLO = (R > 6) ? (R - 6) : 0;
    constexpr int OHI = (R < RPT - 1) ? R : (RPT - 1);
    #pragma unroll
    for (int o = OLO; o <= OHI; ++o) {
        const int dy = R - o;
        #pragma unroll
        for (int dx = 0; dx < 7; ++dx) {
            const float wv = w[dy * 7 + dx];
            acc[o].x = fmaf(wv, v[dx + 1], acc[o].x);
            acc[o].y = fmaf(wv, v[dx + 2], acc[o].y);
            acc[o].z = fmaf(wv, v[dx + 3], acc[o].z);
            acc[o].w = fmaf(wv, v[dx + 4], acc[o].w);
        }
    }
}

template<int R>
__device__ __forceinline__ void conv_rows(const float* __restrict__ base,
                                          const float (&w)[KK],
                                          float4 (&acc)[RPT]) {
    conv_row_step<R>(base + R * SSTRIDE, w, acc);
    if constexpr (R + 1 < IN_ROWS)
        conv_rows<R + 1>(base, w, acc);
}

__global__ void __launch_bounds__(256, 2)
dwconv_kernel(const float* __restrict__ x, float* __restrict__ out, int ch0) {
    __shared__ __align__(16) float buf0[SROWS * SSTRIDE];
    __shared__ __align__(16) float buf1[SROWS * SSTRIDE];
    __shared__ float wsh[KK];

    const int ch = ch0 + blockIdx.z;
    const int x0 = blockIdx.x * TILE_W;
    const int ybase = blockIdx.y * 128;
    const int tx = threadIdx.x, ty = threadIdx.y;
    const int tid = ty * 32 + tx;

    const float* __restrict__ xc = x + (size_t)ch * HWv;

    if (tid < KK) wsh[tid] = g_wbuf[ch * KK + tid];

    load_tile_async(buf0, xc, x0, ybase, tx, ty);
    asm volatile("cp.async.commit_group;");

    float w[KK];
    const int col = tx * CPT;
    const int rbase = ty * RPT;

    #pragma unroll 1
    for (int t = 0; t < NT; ++t) {
        asm volatile("cp.async.wait_group 0;");
        __syncthreads();

        if (t == 0) {
            #pragma unroll
            for (int k = 0; k < KK; ++k) w[k] = wsh[k];
        }

        if (t + 1 < NT) {
            load_tile_async((t & 1) ? buf0 : buf1, xc, x0, ybase + (t + 1) * TILE_H, tx, ty);
            asm volatile("cp.async.commit_group;");
        }

        const float* __restrict__ cur = (t & 1) ? buf1 : buf0;

        float4 acc[RPT];
        #pragma unroll
        for (int o = 0; o < RPT; ++o) acc[o] = make_float4(0.f, 0.f, 0.f, 0.f);

        conv_rows<0>(&cur[rbase * SSTRIDE + col], w, acc);

        const int y0 = ybase + t * TILE_H;
        float* __restrict__ oc = out + (size_t)ch * HWv + (size_t)(y0 + rbase) * Wv + x0 + col;
        #pragma unroll
        for (int o = 0; o < RPT; ++o)
            *reinterpret_cast<float4*>(oc + o * Wv) = acc[o];
    }
}

// ---------------------------------------------------------------------------
// Launch: two batch-groups pipelined on forked streams so group B's GAP/MLP
// hide under group A's (compute-bound) conv, and convB fills convA's tail.
// ---------------------------------------------------------------------------
extern "C" void kernel_launch(void* const* d_in, const int* in_sizes, int n_in,
                              void* d_out, int out_size) {
    const float* x  = (const float*)d_in[0];
    const float* w1 = (const float*)d_in[1];
    const float* b1 = (const float*)d_in[2];
    const float* w2 = (const float*)d_in[3];
    const float* b2 = (const float*)d_in[4];
    float* out = (float*)d_out;

    cudaStream_t s1, s2, s3;
    cudaStreamCreateWithFlags(&s1, cudaStreamNonBlocking);
    cudaStreamCreateWithFlags(&s2, cudaStreamNonBlocking);
    cudaStreamCreateWithFlags(&s3, cudaStreamNonBlocking);
    cudaEvent_t e0, eA, eB, eCA, eCB;
    cudaEventCreateWithFlags(&e0,  cudaEventDisableTiming);
    cudaEventCreateWithFlags(&eA,  cudaEventDisableTiming);
    cudaEventCreateWithFlags(&eB,  cudaEventDisableTiming);
    cudaEventCreateWithFlags(&eCA, cudaEventDisableTiming);
    cudaEventCreateWithFlags(&eCB, cudaEventDisableTiming);

    // Fork from the capture (default) stream.
    cudaEventRecord(e0, 0);
    cudaStreamWaitEvent(s1, e0, 0);

    // Producer chain: group A then group B.
    gap_kernel<<<512, 512, 0, s1>>>(x, 0);
    mlp_kernel<<<64, 256, 0, s1>>>(w1, b1, w2, b2, 0);
    cudaEventRecord(eA, s1);
    gap_kernel<<<512, 512, 0, s1>>>(x, 512);
    mlp_kernel<<<64, 256, 0, s1>>>(w1, b1, w2, b2, 8);
    cudaEventRecord(eB, s1);

    // Conv A (channels 0..511) as soon as its weights exist.
    cudaStreamWaitEvent(s2, eA, 0);
    dwconv_kernel<<<dim3(2, 2, 512), dim3(32, 8), 0, s2>>>(x, out, 0);
    cudaEventRecord(eCA, s2);

    // Conv B (channels 512..1023).
    cudaStreamWaitEvent(s3, eB, 0);
    dwconv_kernel<<<dim3(2, 2, 512), dim3(32, 8), 0, s3>>>(x, out, 512);
    cudaEventRecord(eCB, s3);

    // Join back into the capture stream.
    cudaStreamWaitEvent(0, eCA, 0);
    cudaStreamWaitEvent(0, eCB, 0);

    cudaEventDestroy(e0);  cudaEventDestroy(eA);  cudaEventDestroy(eB);
    cudaEventDestroy(eCA); cudaEventDestroy(eCB);
    cudaStreamDestroy(s1); cudaStreamDestroy(s2); cudaStreamDestroy(s3);
}

// round 16
// speedup vs baseline: 1.0249x; 1.0249x over previous
#include <cuda_runtime.h>
#include <math.h>

// Problem constants
#define Bv   16
#define Cv   64
#define Hv   256
#define Wv   256
#define Kv   7
#define HIDv 16
#define NCH  (Bv * Cv)          // 1024 channels
#define HWv  (Hv * Wv)          // 65536
#define KK   (Kv * Kv)          // 49
#define COLS (Cv * KK)          // 3136

// Conv tiling: persistent block over 4 vertical tiles of 128x32.
#define TILE_W 128
#define TILE_H 32
#define NT 4
#define CPT 4
#define RPT 4
#define IN_ROWS (RPT + 6)
#define SROWS (TILE_H + 6)       // 38
#define SSTRIDE 136              // smem col c holds global col x0-4+c

// Scratch (no cudaMalloc allowed)
__device__ float g_pooled[NCH];
__device__ float g_wbuf[NCH * KK];
__device__ unsigned g_cnt[Bv];   // per-batch arrival counters.
                                 // mod-64 test is replay-safe: each graph replay
                                 // adds exactly 64 arrivals per batch.

// ---------------------------------------------------------------------------
// Kernel 1: fused GAP + last-block MLP.
// One block per channel (512 thr). The 64th block to finish within a batch
// computes that batch's MLP (hdn + 3136-col layer + sigmoid) in-kernel,
// overlapped with the remaining GAP blocks of other batches.
// ---------------------------------------------------------------------------
__global__ void __launch_bounds__(512)
gapmlp_kernel(const float* __restrict__ x,
              const float* __restrict__ w1, const float* __restrict__ b1,
              const float* __restrict__ w2, const float* __restrict__ b2) {
    const int ch = blockIdx.x;
    const int batch = ch >> 6;
    const int tid = threadIdx.x;

    // ---- GAP over this channel ----
    const float4* p = reinterpret_cast<const float4*>(x + (size_t)ch * HWv);
    float s = 0.f;
    #pragma unroll 8
    for (int i = tid; i < HWv / 4; i += 512) {
        float4 v = p[i];
        s += (v.x + v.y) + (v.z + v.w);
    }
    #pragma unroll
    for (int off = 16; off > 0; off >>= 1)
        s += __shfl_xor_sync(0xffffffffu, s, off);
    __shared__ float red[16];
    const int lane = tid & 31, wid = tid >> 5;
    if (lane == 0) red[wid] = s;
    __syncthreads();

    __shared__ bool is_last;
    if (tid == 0) {
        float t = 0.f;
        #pragma unroll
        for (int i = 0; i < 16; ++i) t += red[i];
        g_pooled[ch] = t * (1.0f / (float)HWv);
        __threadfence();
        unsigned old = atomicAdd(&g_cnt[batch], 1u);
        is_last = (((old + 1u) & 63u) == 0u);
    }
    __syncthreads();
    if (!is_last) return;

    // ---- This block closes the batch: compute its MLP ----
    __threadfence();   // acquire: all 64 pooled values are visible

    __shared__ float sp[Cv];
    __shared__ float sh[HIDv];
    if (tid < Cv) sp[tid] = g_pooled[batch * Cv + tid];
    __syncthreads();

    if (tid < HIDv) {
        float v = b1[tid];
        #pragma unroll
        for (int c = 0; c < Cv; ++c)
            v = fmaf(sp[c], w1[c * HIDv + tid], v);
        sh[tid] = 0.5f * v * (1.0f + erff(v * 0.70710678118654752f));
    }
    __syncthreads();

    float* __restrict__ wb = g_wbuf + (size_t)batch * COLS;
    for (int j = tid; j < COLS; j += 512) {
        float v = b2[j];
        #pragma unroll
        for (int h = 0; h < HIDv; ++h)
            v = fmaf(sh[h], w2[h * COLS + j], v);
        wb[j] = 1.0f / (1.0f + __expf(-v));
    }
}

// ---------------------------------------------------------------------------
// cp.async helpers + vectorized tile loader (R11, proven)
// ---------------------------------------------------------------------------
__device__ __forceinline__ int reflect_idx(int i) {
    return i < 0 ? -i : (i > 255 ? 510 - i : i);
}
__device__ __forceinline__ void cpasync4(float* dst_smem, const float* src_gmem) {
    unsigned dst = (unsigned)__cvta_generic_to_shared(dst_smem);
    asm volatile("cp.async.ca.shared.global [%0], [%1], 4;" :: "r"(dst), "l"(src_gmem));
}
__device__ __forceinline__ void cpasync16(float* dst_smem, const float* src_gmem) {
    unsigned dst = (unsigned)__cvta_generic_to_shared(dst_smem);
    asm volatile("cp.async.cg.shared.global [%0], [%1], 16;" :: "r"(dst), "l"(src_gmem));
}
__device__ __forceinline__ void load_tile_async(float* __restrict__ buf,
                                                const float* __restrict__ xc,
                                                int x0, int y0, int tx, int ty) {
    for (int r = ty; r < SROWS; r += 8) {
        const int gr = reflect_idx(y0 - 3 + r);
        const float* __restrict__ rowp = xc + gr * Wv;
        float* __restrict__ srow = buf + r * SSTRIDE;
        cpasync16(srow + 4 + 4 * tx, rowp + x0 + 4 * tx);
        if (tx < 6) {
            const int c = (tx < 3) ? (tx + 1) : (129 + tx);
            cpasync4(srow + c, rowp + reflect_idx(x0 - 4 + c));
        }
    }
}

// ---------------------------------------------------------------------------
// Kernel 2: depthwise 7x7 conv, reflect padding (R11 — proven FP32 FMA floor).
// ---------------------------------------------------------------------------
template<int R>
__device__ __forceinline__ void conv_row_step(const float* __restrict__ row,
                                              const float (&w)[KK],
                                              float4 (&acc)[RPT]) {
    float v[12];
    {
        float4 t0 = *reinterpret_cast<const float4*>(row);
        float4 t1 = *reinterpret_cast<const float4*>(row + 4);
        float4 t2 = *reinterpret_cast<const float4*>(row + 8);
        v[0] = t0.x; v[1] = t0.y; v[2]  = t0.z; v[3]  = t0.w;
        v[4] = t1.x; v[5] = t1.y; v[6]  = t1.z; v[7]  = t1.w;
        v[8] = t2.x; v[9] = t2.y; v[10] = t2.z; v[11] = t2.w;
    }
    constexpr int OLO = (R > 6) ? (R - 6) : 0;
    constexpr int OHI = (R < RPT - 1) ? R : (RPT - 1);
    #pragma unroll
    for (int o = OLO; o <= OHI; ++o) {
        const int dy = R - o;
        #pragma unroll
        for (int dx = 0; dx < 7; ++dx) {
            const float wv = w[dy * 7 + dx];
            acc[o].x = fmaf(wv, v[dx + 1], acc[o].x);
            acc[o].y = fmaf(wv, v[dx + 2], acc[o].y);
            acc[o].z = fmaf(wv, v[dx + 3], acc[o].z);
            acc[o].w = fmaf(wv, v[dx + 4], acc[o].w);
        }
    }
}

template<int R>
__device__ __forceinline__ void conv_rows(const float* __restrict__ base,
                                          const float (&w)[KK],
                                          float4 (&acc)[RPT]) {
    conv_row_step<R>(base + R * SSTRIDE, w, acc);
    if constexpr (R + 1 < IN_ROWS)
        conv_rows<R + 1>(base, w, acc);
}

__global__ void __launch_bounds__(256, 2)
dwconv_kernel(const float* __restrict__ x, float* __restrict__ out) {
    __shared__ __align__(16) float buf0[SROWS * SSTRIDE];
    __shared__ __align__(16) float buf1[SROWS * SSTRIDE];
    __shared__ float wsh[KK];

    const int ch = blockIdx.z;
    const int x0 = blockIdx.x * TILE_W;      // 0 or 128
    const int ybase = blockIdx.y * 128;      // 0 or 128
    const int tx = threadIdx.x, ty = threadIdx.y;
    const int tid = ty * 32 + tx;

    const float* __restrict__ xc = x + (size_t)ch * HWv;

    // g_wbuf layout: [batch][c*49+k] == [(b*64+c)*49 + k]
    if (tid < KK) wsh[tid] = g_wbuf[(size_t)ch * KK + tid];

    load_tile_async(buf0, xc, x0, ybase, tx, ty);
    asm volatile("cp.async.commit_group;");

    float w[KK];
    const int col = tx * CPT;                // 0..124
    const int rbase = ty * RPT;              // 0..28

    #pragma unroll 1
    for (int t = 0; t < NT; ++t) {
        asm volatile("cp.async.wait_group 0;");
        __syncthreads();

        if (t == 0) {
            #pragma unroll
            for (int k = 0; k < KK; ++k) w[k] = wsh[k];
        }

        if (t + 1 < NT) {
            load_tile_async((t & 1) ? buf0 : buf1, xc, x0, ybase + (t + 1) * TILE_H, tx, ty);
            asm volatile("cp.async.commit_group;");
        }

        const float* __restrict__ cur = (t & 1) ? buf1 : buf0;

        float4 acc[RPT];
        #pragma unroll
        for (int o = 0; o < RPT; ++o) acc[o] = make_float4(0.f, 0.f, 0.f, 0.f);

        conv_rows<0>(&cur[rbase * SSTRIDE + col], w, acc);

        const int y0 = ybase + t * TILE_H;
        float* __restrict__ oc = out + (size_t)ch * HWv + (size_t)(y0 + rbase) * Wv + x0 + col;
        #pragma unroll
        for (int o = 0; o < RPT; ++o)
            *reinterpret_cast<float4*>(oc + o * Wv) = acc[o];
    }
}

// ---------------------------------------------------------------------------
// Launch: single stream, two kernels. No stream/event creation (alloc guard).
// ---------------------------------------------------------------------------
extern "C" void kernel_launch(void* const* d_in, const int* in_sizes, int n_in,
                              void* d_out, int out_size) {
    const float* x  = (const float*)d_in[0];
    const float* w1 = (const float*)d_in[1];
    const float* b1 = (const float*)d_in[2];
    const float* w2 = (const float*)d_in[3];
    const float* b2 = (const float*)d_in[4];
    float* out = (float*)d_out;

    gapmlp_kernel<<<NCH, 512>>>(x, w1, b1, w2, b2);
    dwconv_kernel<<<dim3(2, 2, NCH), dim3(32, 8)>>>(x, out);
}